// round 1
// baseline (speedup 1.0000x reference)
#include <cuda_runtime.h>
#include <cstdint>

#define Nn 8
#define Cc 128
#define Ll 1024
#define Kk 100
#define INV_TEMP 2.0f
#define EPSf 1e-8f

// Scratch: transposed z and c ([N, L, C], contiguous 512B rows) + reciprocal norms.
__device__ float g_zseq[Nn * Ll * Cc];
__device__ float g_cseq[Nn * Ll * Cc];
__device__ float g_zrn[Nn * Ll];
__device__ float g_crn[Nn * Ll];

// Transpose [C, ld] (per n) -> [L, C], taking source columns [col_off, col_off+L).
// which==0 -> g_zseq, which==1 -> g_cseq.
__global__ void transpose_k(const float* __restrict__ src, int ld_src, int col_off, int which) {
    __shared__ float tile[32][33];
    int n   = blockIdx.z;
    int t0  = blockIdx.x * 32;   // position (L) tile
    int ch0 = blockIdx.y * 32;   // channel tile
    const float* s = src + (size_t)n * Cc * ld_src;
    float* d = (which == 0 ? g_zseq : g_cseq) + (size_t)n * Ll * Cc;
    int tx = threadIdx.x, ty = threadIdx.y;  // blockDim = (32, 8)
#pragma unroll
    for (int i = 0; i < 32; i += 8)
        tile[ty + i][tx] = s[(size_t)(ch0 + ty + i) * ld_src + col_off + t0 + tx];
    __syncthreads();
#pragma unroll
    for (int i = 0; i < 32; i += 8)
        d[(size_t)(t0 + ty + i) * Cc + ch0 + tx] = tile[tx][ty + i];
}

// One warp per row: reciprocal norm 1/max(||v||, EPS) for all 2*N*L rows.
__global__ void norm_k() {
    int gw   = (blockIdx.x * blockDim.x + threadIdx.x) >> 5;
    int lane = threadIdx.x & 31;
    const int total = 2 * Nn * Ll;
    if (gw >= total) return;
    bool is_c = (gw >= Nn * Ll);
    int row = is_c ? gw - Nn * Ll : gw;
    const float4* base = (const float4*)(is_c ? g_cseq : g_zseq);
    float4 v = base[(size_t)row * 32 + lane];
    float s = v.x * v.x + v.y * v.y + v.z * v.z + v.w * v.w;
#pragma unroll
    for (int o = 16; o; o >>= 1) s += __shfl_xor_sync(0xffffffffu, s, o);
    if (lane == 0) {
        float rn = 1.0f / fmaxf(sqrtf(s), EPSf);
        (is_c ? g_crn : g_zrn)[row] = rn;
    }
}

// One block per output row (n, t). 4 warps; warp-per-similarity over j in [0, K].
__global__ void __launch_bounds__(128) main_k(const int* __restrict__ neg_inds,
                                              float* __restrict__ out) {
    int r    = blockIdx.x;         // 0..N*L-1
    int n    = r >> 10;            // r / L
    int t    = r & (Ll - 1);
    int warp = threadIdx.x >> 5;   // 0..3
    int lane = threadIdx.x & 31;

    __shared__ float slog[Kk + 1];

    const float4* cvp = (const float4*)g_cseq + (size_t)r * 32;
    float4 cv = cvp[lane];
    float scale = g_crn[r] * INV_TEMP;   // 1/(c_norm * TEMP)

    const int* ni = neg_inds + (size_t)r * Kk;
    const float4* zbase = (const float4*)g_zseq + ((size_t)n << 10) * 32;

    for (int j = warp; j <= Kk; j += 4) {
        int idx = (j == 0) ? t : ni[j - 1];
        float4 zv = zbase[(size_t)idx * 32 + lane];
        float d = cv.x * zv.x + cv.y * zv.y + cv.z * zv.z + cv.w * zv.w;
        bool eq = (cv.x == zv.x) & (cv.y == zv.y) & (cv.z == zv.z) & (cv.w == zv.w);
#pragma unroll
        for (int o = 16; o; o >>= 1) d += __shfl_xor_sync(0xffffffffu, d, o);
        unsigned all_eq = __all_sync(0xffffffffu, eq);
        float logit = d * scale * g_zrn[(n << 10) + idx];
        if (j > 0 && all_eq) logit = __int_as_float(0xff800000u);  // -inf
        if (lane == 0) slog[j] = logit;
    }
    __syncthreads();
    if (threadIdx.x <= Kk)
        out[(size_t)r * (Kk + 1) + threadIdx.x] = slog[threadIdx.x];
}

extern "C" void kernel_launch(void* const* d_in, const int* in_sizes, int n_in,
                              void* d_out, int out_size) {
    const float* z  = (const float*)d_in[0];  // [N, C, L]
    const float* c  = (const float*)d_in[1];  // [N, C, L+1]
    const int*   ni = (const int*)d_in[2];    // [N, L, K]
    float* out = (float*)d_out;               // [N*L, K+1]

    dim3 tb(32, 8);
    dim3 tg(Ll / 32, Cc / 32, Nn);
    transpose_k<<<tg, tb>>>(z, Ll, 0, 0);
    transpose_k<<<tg, tb>>>(c, Ll + 1, 1, 1);

    // 2*N*L rows, 8 warps per 256-thread block
    int nrows = 2 * Nn * Ll;
    int nblk = (nrows * 32 + 255) / 256;
    norm_k<<<nblk, 256>>>();

    main_k<<<Nn * Ll, 128>>>(ni, out);
}

// round 2
// speedup vs baseline: 1.4297x; 1.4297x over previous
#include <cuda_runtime.h>
#include <cstdint>

#define Nn 8
#define Cc 128
#define Ll 1024
#define Kk 100
#define INV_TEMP 2.0f
#define EPSf 1e-8f

// Scratch: transposed z and c ([N, L, C], contiguous 512B rows) + reciprocal norms.
__device__ float g_zseq[Nn * Ll * Cc];
__device__ float g_cseq[Nn * Ll * Cc];
__device__ float g_zrn[Nn * Ll];
__device__ float g_crn[Nn * Ll];

// Transpose [C, ld] (per n) -> [L, C], taking source columns [col_off, col_off+L).
__global__ void transpose_k(const float* __restrict__ src, int ld_src, int col_off, int which) {
    __shared__ float tile[32][33];
    int n   = blockIdx.z;
    int t0  = blockIdx.x * 32;
    int ch0 = blockIdx.y * 32;
    const float* s = src + (size_t)n * Cc * ld_src;
    float* d = (which == 0 ? g_zseq : g_cseq) + (size_t)n * Ll * Cc;
    int tx = threadIdx.x, ty = threadIdx.y;  // blockDim = (32, 8)
#pragma unroll
    for (int i = 0; i < 32; i += 8)
        tile[ty + i][tx] = s[(size_t)(ch0 + ty + i) * ld_src + col_off + t0 + tx];
    __syncthreads();
#pragma unroll
    for (int i = 0; i < 32; i += 8)
        d[(size_t)(t0 + ty + i) * Cc + ch0 + tx] = tile[tx][ty + i];
}

// One warp per row: reciprocal norm 1/max(||v||, EPS) for all 2*N*L rows.
__global__ void norm_k() {
    int gw   = (blockIdx.x * blockDim.x + threadIdx.x) >> 5;
    int lane = threadIdx.x & 31;
    const int total = 2 * Nn * Ll;
    if (gw >= total) return;
    bool is_c = (gw >= Nn * Ll);
    int row = is_c ? gw - Nn * Ll : gw;
    const float4* base = (const float4*)(is_c ? g_cseq : g_zseq);
    float4 v = base[(size_t)row * 32 + lane];
    float s = v.x * v.x + v.y * v.y + v.z * v.z + v.w * v.w;
#pragma unroll
    for (int o = 16; o; o >>= 1) s += __shfl_xor_sync(0xffffffffu, s, o);
    if (lane == 0) {
        float rn = 1.0f / fmaxf(sqrtf(s), EPSf);
        (is_c ? g_crn : g_zrn)[row] = rn;
    }
}

// One block (128 thr) per output row (n, t).
// Warp computes 4 dots concurrently: 8 lanes per dot, lane owns 16 channels.
// All z loads are 4x full 128B lines per LDG instruction (dense wavefronts).
__global__ void __launch_bounds__(128) main_k(const int* __restrict__ neg_inds,
                                              float* __restrict__ out) {
    int r    = blockIdx.x;         // 0..N*L-1
    int n    = r >> 10;
    int t    = r & (Ll - 1);
    int tid  = threadIdx.x;
    int warp = tid >> 5;
    int lane = tid & 31;
    int g    = lane >> 3;          // group within warp (0..3) -> dot slot
    int p    = lane & 7;           // position within group (0..7)

    __shared__ int   sidx[112];
    __shared__ float slog[112];

    // Stage the 101 target indices (slot 0 = positive t, 1..100 = negatives).
    if (tid < 112)
        sidx[tid] = (tid == 0 || tid > 100) ? t : neg_inds[(size_t)r * Kk + tid - 1];
    __syncthreads();

    // c chunk for this lane: 4 float4 = 16 channels, contiguous per instruction.
    const float4* crow = (const float4*)g_cseq + (size_t)r * 32;
    float4 c0 = crow[p], c1 = crow[8 + p], c2 = crow[16 + p], c3 = crow[24 + p];
    float scale = g_crn[r] * INV_TEMP;   // 1/(c_norm * TEMP)

    const float4* zb  = (const float4*)g_zseq + ((size_t)n << 10) * 32;
    const float*  zrn = g_zrn + (n << 10);

#pragma unroll
    for (int pass = 0; pass < 7; pass++) {
        int j   = pass * 16 + warp * 4 + g;   // 0..111 (>100 are dummy slots)
        int idx = sidx[j];
        const float4* zr = zb + (size_t)idx * 32;
        float4 z0 = zr[p], z1 = zr[8 + p], z2 = zr[16 + p], z3 = zr[24 + p];

        float4 a;
        a.x = c0.x * z0.x; a.y = c0.y * z0.y; a.z = c0.z * z0.z; a.w = c0.w * z0.w;
        a.x += c1.x * z1.x; a.y += c1.y * z1.y; a.z += c1.z * z1.z; a.w += c1.w * z1.w;
        a.x += c2.x * z2.x; a.y += c2.y * z2.y; a.z += c2.z * z2.z; a.w += c2.w * z2.w;
        a.x += c3.x * z3.x; a.y += c3.y * z3.y; a.z += c3.z * z3.z; a.w += c3.w * z3.w;
        float d = (a.x + a.y) + (a.z + a.w);

        // Reduce across the 8 lanes of this group.
        d += __shfl_xor_sync(0xffffffffu, d, 1);
        d += __shfl_xor_sync(0xffffffffu, d, 2);
        d += __shfl_xor_sync(0xffffffffu, d, 4);

        if (p == 0 && j <= Kk)
            slog[j] = d * scale * zrn[idx];
    }
    __syncthreads();
    if (tid <= Kk)
        out[(size_t)r * (Kk + 1) + tid] = slog[tid];
}

extern "C" void kernel_launch(void* const* d_in, const int* in_sizes, int n_in,
                              void* d_out, int out_size) {
    const float* z  = (const float*)d_in[0];  // [N, C, L]
    const float* c  = (const float*)d_in[1];  // [N, C, L+1]
    const int*   ni = (const int*)d_in[2];    // [N, L, K]
    float* out = (float*)d_out;               // [N*L, K+1]

    dim3 tb(32, 8);
    dim3 tg(Ll / 32, Cc / 32, Nn);
    transpose_k<<<tg, tb>>>(z, Ll, 0, 0);
    transpose_k<<<tg, tb>>>(c, Ll + 1, 1, 1);

    int nrows = 2 * Nn * Ll;
    int nblk = (nrows * 32 + 255) / 256;
    norm_k<<<nblk, 256>>>();

    main_k<<<Nn * Ll, 128>>>(ni, out);
}

// round 3
// speedup vs baseline: 1.4606x; 1.0216x over previous
#include <cuda_runtime.h>
#include <cstdint>

#define Nn 8
#define Cc 128
#define Ll 1024
#define Kk 100
#define INV_TEMP 2.0f
#define EPSf 1e-8f

// Scratch: transposed z and c ([N, L, C], contiguous 512B rows) + reciprocal norms.
__device__ float g_zseq[Nn * Ll * Cc];
__device__ float g_cseq[Nn * Ll * Cc];
__device__ float g_zrn[Nn * Ll];
__device__ float g_crn[Nn * Ll];

// Fused transpose for z and c: blockIdx.z in [0, 2N). First N = z, next N = c.
__global__ void transpose2_k(const float* __restrict__ zsrc, const float* __restrict__ csrc) {
    __shared__ float tile[32][33];
    int zz = blockIdx.z;
    bool is_c = zz >= Nn;
    int n = is_c ? zz - Nn : zz;
    int ld      = is_c ? (Ll + 1) : Ll;
    int col_off = is_c ? 1 : 0;
    const float* s = (is_c ? csrc : zsrc) + (size_t)n * Cc * ld;
    float* d = (is_c ? g_cseq : g_zseq) + (size_t)n * Ll * Cc;
    int t0  = blockIdx.x * 32;
    int ch0 = blockIdx.y * 32;
    int tx = threadIdx.x, ty = threadIdx.y;  // blockDim = (32, 8)
#pragma unroll
    for (int i = 0; i < 32; i += 8)
        tile[ty + i][tx] = s[(size_t)(ch0 + ty + i) * ld + col_off + t0 + tx];
    __syncthreads();
#pragma unroll
    for (int i = 0; i < 32; i += 8)
        d[(size_t)(t0 + ty + i) * Cc + ch0 + tx] = tile[tx][ty + i];
}

// One warp per row: reciprocal norm 1/max(||v||, EPS) for all 2*N*L rows.
__global__ void norm_k() {
    int gw   = (blockIdx.x * blockDim.x + threadIdx.x) >> 5;
    int lane = threadIdx.x & 31;
    const int total = 2 * Nn * Ll;
    if (gw >= total) return;
    bool is_c = (gw >= Nn * Ll);
    int row = is_c ? gw - Nn * Ll : gw;
    const float4* base = (const float4*)(is_c ? g_cseq : g_zseq);
    float4 v = base[(size_t)row * 32 + lane];
    float s = v.x * v.x + v.y * v.y + v.z * v.z + v.w * v.w;
#pragma unroll
    for (int o = 16; o; o >>= 1) s += __shfl_xor_sync(0xffffffffu, s, o);
    if (lane == 0) {
        float rn = 1.0f / fmaxf(sqrtf(s), EPSf);
        (is_c ? g_crn : g_zrn)[row] = rn;
    }
}

// Warp-per-row. No smem, no block syncs. 8 lanes per dot, 4 dots per pass,
// 26 passes (slots 0..103; slot 0 = positive, >100 = dummy). Double-buffered:
// pass p+1's gathers are issued before pass p's reduction.
__global__ void __launch_bounds__(256) main_k(const int* __restrict__ neg_inds,
                                              float* __restrict__ out) {
    int warp = threadIdx.x >> 5;
    int r    = (blockIdx.x << 3) + warp;   // 0..N*L-1
    int n    = r >> 10;
    int t    = r & (Ll - 1);
    int lane = threadIdx.x & 31;
    int g    = lane >> 3;                  // dot slot within pass
    int p    = lane & 7;                   // lane within dot

    const float4* crow = (const float4*)g_cseq + (size_t)r * 32;
    float4 c0 = crow[p], c1 = crow[8 + p], c2 = crow[16 + p], c3 = crow[24 + p];
    float scale = g_crn[r] * INV_TEMP;

    const float4* zbase = (const float4*)g_zseq + ((size_t)n << 10) * 32;
    const float*  zrn   = g_zrn + (n << 10);
    const int*    ni    = neg_inds + (size_t)r * Kk;
    float*        orow  = out + (size_t)r * (Kk + 1);

    // Prologue: fetch slot j = g for pass 0.
    int idx = (g == 0) ? t : ni[g - 1];
    const float4* zr = zbase + (size_t)idx * 32;
    float4 z0 = zr[p], z1 = zr[8 + p], z2 = zr[16 + p], z3 = zr[24 + p];
    float  rz = zrn[idx];

#pragma unroll
    for (int pass = 0; pass < 26; pass++) {
        int j = pass * 4 + g;

        // Prefetch next pass (slots j+4; j+4 >= 4 so never the positive).
        float4 y0, y1, y2, y3;
        float  ry = 0.f;
        if (pass < 25) {
            int jn   = j + 4;
            int idxn = (jn <= Kk) ? ni[jn - 1] : t;
            const float4* zn = zbase + (size_t)idxn * 32;
            y0 = zn[p]; y1 = zn[8 + p]; y2 = zn[16 + p]; y3 = zn[24 + p];
            ry = zrn[idxn];
        }

        float a = c0.x * z0.x + c0.y * z0.y + c0.z * z0.z + c0.w * z0.w;
        a += c1.x * z1.x + c1.y * z1.y + c1.z * z1.z + c1.w * z1.w;
        a += c2.x * z2.x + c2.y * z2.y + c2.z * z2.z + c2.w * z2.w;
        a += c3.x * z3.x + c3.y * z3.y + c3.z * z3.z + c3.w * z3.w;

        a += __shfl_xor_sync(0xffffffffu, a, 1);
        a += __shfl_xor_sync(0xffffffffu, a, 2);
        a += __shfl_xor_sync(0xffffffffu, a, 4);

        if (p == 0 && j <= Kk)
            orow[j] = a * scale * rz;

        z0 = y0; z1 = y1; z2 = y2; z3 = y3; rz = ry;
    }
}

extern "C" void kernel_launch(void* const* d_in, const int* in_sizes, int n_in,
                              void* d_out, int out_size) {
    const float* z  = (const float*)d_in[0];  // [N, C, L]
    const float* c  = (const float*)d_in[1];  // [N, C, L+1]
    const int*   ni = (const int*)d_in[2];    // [N, L, K]
    float* out = (float*)d_out;               // [N*L, K+1]

    dim3 tb(32, 8);
    dim3 tg(Ll / 32, Cc / 32, 2 * Nn);
    transpose2_k<<<tg, tb>>>(z, c);

    int nrows = 2 * Nn * Ll;
    int nblk = (nrows * 32 + 255) / 256;
    norm_k<<<nblk, 256>>>();

    main_k<<<(Nn * Ll) / 8, 256>>>(ni, out);
}

// round 4
// speedup vs baseline: 1.8033x; 1.2346x over previous
#include <cuda_runtime.h>
#include <cuda_fp16.h>
#include <cstdint>

#define Nn 8
#define Cc 128
#define Ll 1024
#define Kk 100
#define EPSf 1e-8f

// Normalized fp16 rows, [N, L, C] (256B per row).
__device__ __half g_zh[Nn * Ll * Cc];
__device__ __half g_ch[Nn * Ll * Cc];
// Reciprocal norms (from original layout).
__device__ float g_zrn[Nn * Ll];
__device__ float g_crn[Nn * Ll];

// Compute reciprocal norms from ORIGINAL layout (coalesced over t).
// blockIdx.y: 0 -> z [N,C,L], 1 -> c [N,C,L+1] (cols 1..L).
__global__ void rn_k(const float* __restrict__ z, const float* __restrict__ c) {
    bool is_c = blockIdx.y != 0;
    int nt = blockIdx.x * blockDim.x + threadIdx.x;   // 0..N*L-1
    int n = nt >> 10, t = nt & (Ll - 1);
    int ld = is_c ? (Ll + 1) : Ll;
    const float* s = (is_c ? c : z) + (size_t)n * Cc * ld + (is_c ? 1 : 0) + t;
    float acc = 0.f;
#pragma unroll 16
    for (int ch = 0; ch < Cc; ch++) {
        float v = s[(size_t)ch * ld];
        acc += v * v;
    }
    (is_c ? g_crn : g_zrn)[nt] = 1.0f / fmaxf(sqrtf(acc), EPSf);
}

// Transpose + normalize + fp16 convert. blockIdx.z in [0, 2N): first N = z, next N = c.
__global__ void transpose_half_k(const float* __restrict__ zsrc, const float* __restrict__ csrc) {
    __shared__ float tile[32][33];
    int zz = blockIdx.z;
    bool is_c = zz >= Nn;
    int n = is_c ? zz - Nn : zz;
    int ld      = is_c ? (Ll + 1) : Ll;
    int col_off = is_c ? 1 : 0;
    const float* s = (is_c ? csrc : zsrc) + (size_t)n * Cc * ld;
    __half* d = (is_c ? g_ch : g_zh) + (size_t)n * Ll * Cc;
    const float* rn = (is_c ? g_crn : g_zrn) + (n << 10);
    int t0  = blockIdx.x * 32;
    int ch0 = blockIdx.y * 32;
    int tx = threadIdx.x, ty = threadIdx.y;  // blockDim = (32, 8)
#pragma unroll
    for (int i = 0; i < 32; i += 8)
        tile[ty + i][tx] = s[(size_t)(ch0 + ty + i) * ld + col_off + t0 + tx];
    __syncthreads();
#pragma unroll
    for (int i = 0; i < 32; i += 8) {
        int t = t0 + ty + i;
        d[(size_t)t * Cc + ch0 + tx] = __float2half(tile[tx][ty + i] * rn[t]);
    }
}

// Warp-per-row. 8 lanes per dot (lane owns 16 channels = 2 uint4 of half),
// 4 dots per pass, 26 passes. Double-buffered gather.
__global__ void __launch_bounds__(256) main_k(const int* __restrict__ neg_inds,
                                              float* __restrict__ out) {
    int warp = threadIdx.x >> 5;
    int r    = (blockIdx.x << 3) + warp;   // 0..N*L-1
    int n    = r >> 10;
    int t    = r & (Ll - 1);
    int lane = threadIdx.x & 31;
    int g    = lane >> 3;                  // dot slot within pass
    int p    = lane & 7;                   // lane within dot

    // c chunk: 16 channels for this lane, converted to fp32 once.
    const uint4* crow = (const uint4*)(g_ch + (size_t)r * Cc);  // 16 uint4 per row
    uint4 ca = crow[2 * p], cb = crow[2 * p + 1];
    float2 cf[8];
    {
        const __half2* h;
        h = (const __half2*)&ca;
        cf[0] = __half22float2(h[0]); cf[1] = __half22float2(h[1]);
        cf[2] = __half22float2(h[2]); cf[3] = __half22float2(h[3]);
        h = (const __half2*)&cb;
        cf[4] = __half22float2(h[0]); cf[5] = __half22float2(h[1]);
        cf[6] = __half22float2(h[2]); cf[7] = __half22float2(h[3]);
    }

    const uint4* zbase = (const uint4*)(g_zh + ((size_t)n << 10) * Cc);
    const int*   ni    = neg_inds + (size_t)r * Kk;
    float*       orow  = out + (size_t)r * (Kk + 1);

    // Prologue: fetch slot j = g for pass 0.
    int idx = (g == 0) ? t : ni[g - 1];
    uint4 z0 = zbase[(size_t)idx * 16 + 2 * p];
    uint4 z1 = zbase[(size_t)idx * 16 + 2 * p + 1];

#pragma unroll
    for (int pass = 0; pass < 26; pass++) {
        int j = pass * 4 + g;

        // Prefetch next pass (slots j+4 are never the positive).
        uint4 y0, y1;
        if (pass < 25) {
            int jn   = j + 4;
            int idxn = (jn <= Kk) ? ni[jn - 1] : t;
            y0 = zbase[(size_t)idxn * 16 + 2 * p];
            y1 = zbase[(size_t)idxn * 16 + 2 * p + 1];
        }

        float a = 0.f, b = 0.f;
        {
            const __half2* h = (const __half2*)&z0;
#pragma unroll
            for (int q = 0; q < 4; q++) {
                float2 zf = __half22float2(h[q]);
                a = fmaf(cf[q].x, zf.x, a);
                b = fmaf(cf[q].y, zf.y, b);
            }
            h = (const __half2*)&z1;
#pragma unroll
            for (int q = 0; q < 4; q++) {
                float2 zf = __half22float2(h[q]);
                a = fmaf(cf[4 + q].x, zf.x, a);
                b = fmaf(cf[4 + q].y, zf.y, b);
            }
        }
        a += b;

        a += __shfl_xor_sync(0xffffffffu, a, 1);
        a += __shfl_xor_sync(0xffffffffu, a, 2);
        a += __shfl_xor_sync(0xffffffffu, a, 4);

        if (p == 0 && j <= Kk)
            orow[j] = a * 2.0f;   // / (c_norm * z_norm) folded in; / TEMP = *2

        z0 = y0; z1 = y1;
    }
}

extern "C" void kernel_launch(void* const* d_in, const int* in_sizes, int n_in,
                              void* d_out, int out_size) {
    const float* z  = (const float*)d_in[0];  // [N, C, L]
    const float* c  = (const float*)d_in[1];  // [N, C, L+1]
    const int*   ni = (const int*)d_in[2];    // [N, L, K]
    float* out = (float*)d_out;               // [N*L, K+1]

    dim3 rng((Nn * Ll) / 256, 2);
    rn_k<<<rng, 256>>>(z, c);

    dim3 tb(32, 8);
    dim3 tg(Ll / 32, Cc / 32, 2 * Nn);
    transpose_half_k<<<tg, tb>>>(z, c);

    main_k<<<(Nn * Ll) / 8, 256>>>(ni, out);
}